// round 11
// baseline (speedup 1.0000x reference)
#include <cuda_runtime.h>
#include <math.h>

#define NEGV  (-1e30f)
#define LOG2E 1.4426950408889634f
#define LN2   0.6931471805599453f
#define NW    4
#define BLOCK 128              // 1 pair per thread; warp w <-> SMSP w
#define RSLOT 64               // emission ring slots (per warp)
#define EROW  36               // floats per row: [0]=blank, [1+lane]=label
#define BRING 32               // boundary ring slots
#define MAXB  64

__device__ float g_partial[MAXB];
__device__ float g_bt[MAXB][260];     // bt(tm+1, s), natural order; [257..259] pad
__device__ int   g_flag[MAXB];        // zero-init; backward sets, forward resets
__device__ int   g_ctr = 0;

__device__ __forceinline__ float ex2f(float x) {
    float r; asm("ex2.approx.ftz.f32 %0, %1;" : "=f"(r) : "f"(x)); return r;
}
__device__ __forceinline__ float lg2f(float x) {
    float r; asm("lg2.approx.ftz.f32 %0, %1;" : "=f"(r) : "f"(x)); return r;
}
__device__ __forceinline__ float lse2(float a, float b) {   // log2 domain
    float m = fmaxf(a, b);
    return m + lg2f(1.0f + ex2f(fminf(a, b) - m));
}
__device__ __forceinline__ unsigned smem_u32(const void* p) {
    return (unsigned)__cvta_generic_to_shared(p);
}
__device__ __forceinline__ void cp4(unsigned dst, const float* src) {
    asm volatile("cp.async.ca.shared.global [%0], [%1], 4;\n" :: "r"(dst), "l"(src));
}
__device__ __forceinline__ void cp_commit() { asm volatile("cp.async.commit_group;\n"); }
__device__ __forceinline__ void cp_wait2()  { asm volatile("cp.async.wait_group 2;\n"); }

__global__ void __launch_bounds__(BLOCK, 1)
ctc_bidir(const float* __restrict__ lp,      // [T, B, V] log-probs (ln domain)
          const int*   __restrict__ targets, // [B, L]
          const int*   __restrict__ ilen,    // [B]
          float* __restrict__ out,
          int T, int B, int V, int L)
{
    const int b    = blockIdx.x >> 1;
    const int dir  = blockIdx.x & 1;          // 0 = forward, 1 = backward
    const int tid  = threadIdx.x;
    const int w    = tid >> 5;
    const int lane = tid & 31;

    __shared__ float sh_e[NW][RSLOT][EROW];   // warp-private emission rings
    __shared__ float sh_bnd[NW - 1][BRING];   // boundary a_odd(t) per warp seam
    __shared__ float sh_red[NW];
    __shared__ int   s_last;

    int Tb = ilen[b];
    if (Tb > T) Tb = T;
    const int tm = Tb >> 1;
    const int N  = dir ? (Tb - tm - 2) : tm;  // live steps t = 1..N

    // thread owns pair = tid (states 2p, 2p+1 in this direction's coords)
    const int pair = tid;
    const int own  = dir ? (L - 1 - pair) : pair;
    const int lab  = targets[b * L + own];
    bool skip = false;
    if (pair >= 1) {
        const int oth = dir ? (own + 1) : (own - 1);
        skip = (targets[b * L + oth] != lab);
    }
    const float skipf = skip ? 1.0f : 0.0f;

    const size_t strideT = (size_t)B * (size_t)V;
    const float* gb = lp + (size_t)b * (size_t)V;   // blank column
    const float* gl = gb + lab;                     // own label column
    const unsigned dstL = smem_u32(&sh_e[w][0][1 + lane]);
    const unsigned dstB = smem_u32(&sh_e[w][0][0]);
    const unsigned rowB = EROW * sizeof(float);

    #define TOF(k) (dir ? (Tb - 1 - (k)) : (k))

    // ---- prologue: windows for rounds 0..2 (skewed), 1 group per window ----
    #pragma unroll
    for (int k = 0; k < 3; ++k) {
        const int tbase = 8 * (k - w) + 1;
        if (w == 0 && k == 0) {               // t=0 emission for init (slot 0)
            cp4(dstL, gl + (size_t)TOF(0) * strideT);
            if (lane == 0) cp4(dstB, gb + (size_t)TOF(0) * strideT);
        }
        #pragma unroll
        for (int i = 0; i < 8; ++i) {
            const int t = tbase + i;
            if (t >= 1 && t <= N) {
                const unsigned so = (unsigned)(t & (RSLOT - 1)) * rowB;
                cp4(dstL + so, gl + (size_t)TOF(t) * strideT);
                if (lane == 0) cp4(dstB + so, gb + (size_t)TOF(t) * strideT);
            }
        }
        cp_commit();
    }
    cp_wait2();       // window 0 (incl. t=0) complete
    __syncwarp();     // lane0's blank copies visible warp-wide

    // ---- init (t=0): states 0,1 live (both dirs via reflection) ----
    float a_even = NEGV, a_odd = NEGV;
    if (tid == 0) { a_even = sh_e[0][0][0] * LOG2E; a_odd = sh_e[0][0][1] * LOG2E; }
    float a_fin = NEGV;                        // pair-128 even state (tid 127 only)
    const bool finT = (tid == BLOCK - 1);
    const bool w0   = (w == 0);

    for (int i = tid; i < (NW - 1) * BRING; i += BLOCK)
        ((float*)sh_bnd)[i] = NEGV;            // boundary at t<=0 is NEG
    __syncthreads();

    // ---- skewed main loop: warp w round r covers t in [8(r-w)+1, 8(r-w)+8] ----
    const int R_tot = ((N + 7) >> 3) + NW - 1;
    const float* bbase = sh_bnd[w0 ? 0 : (w - 1)];
    for (int r = 0; r < R_tot; ++r) {
        const int tbase = 8 * (r - w) + 1;

        // issue prefetch for window r+3 (one group)
        #pragma unroll
        for (int i = 0; i < 8; ++i) {
            const int tp = tbase + 24 + i;
            if (tp >= 1 && tp <= N) {
                const unsigned so = (unsigned)(tp & (RSLOT - 1)) * rowB;
                cp4(dstL + so, gl + (size_t)TOF(tp) * strideT);
                if (lane == 0) cp4(dstB + so, gb + (size_t)TOF(tp) * strideT);
            }
        }
        cp_commit();

        // preload emissions + seam boundary values (uniform, off-chain)
        float eb[8], el[8], bnd[8];
        #pragma unroll
        for (int i = 0; i < 8; ++i) {
            const int slot = (tbase + i) & (RSLOT - 1);
            eb[i] = sh_e[w][slot][0];
            el[i] = sh_e[w][slot][1 + lane];
            float bv = bbase[(tbase + i - 1) & (BRING - 1)];
            bnd[i] = w0 ? NEGV : bv;
        }

        float ov[8];                           // seam publish buffer
        #pragma unroll
        for (int i = 0; i < 8; ++i) {
            const int t = tbase + i;

            float po = __shfl_up_sync(0xFFFFFFFFu, a_odd, 1);
            po = (lane == 0) ? bnd[i] : po;    // SEL, no branch

            const float qm = fmaxf(a_even, a_odd);
            const float m  = fmaxf(qm, po);
            const float x  = ex2f(a_even - m);
            const float z  = ex2f(a_odd  - m);
            const float y  = ex2f(po     - m);

            float ne = fmaf(eb[i], LOG2E, m + lg2f(x + y));
            float no = fmaf(el[i], LOG2E, m + lg2f(fmaf(skipf, y, x + z)));
            ne = fmaxf(ne, NEGV);
            no = fmaxf(no, NEGV);

            // pair-128 even state: computed by ALL lanes (branchless), used on finT
            float nf = fmaxf(fmaf(eb[i], LOG2E, lse2(a_fin, a_odd)), NEGV);

            const bool live = (t >= 1) && (t <= N);
            a_even = live ? ne : a_even;
            a_odd  = live ? no : a_odd;
            a_fin  = live ? nf : a_fin;
            ov[i]  = a_odd;
        }

        // publish seam values: ONE divergent region per round
        if (w < NW - 1 && lane == 31) {
            #pragma unroll
            for (int i = 0; i < 8; ++i)
                sh_bnd[w][(tbase + i) & (BRING - 1)] = ov[i];
        }

        cp_wait2();       // window r+1 complete
        __syncwarp();     // lane0's blank copies visible warp-wide
        __syncthreads();  // seam publishes visible cross-warp
    }

    if (dir) {
        // ---- backward: publish bt(tm+1, s) in natural order ----
        g_bt[b][255 - 2 * pair] = a_odd;       // s = 255,253,...,1
        g_bt[b][256 - 2 * pair] = a_even;      // s = 256,254,...,2
        if (finT)    g_bt[b][0] = a_fin;       // s = 0
        if (tid < 3) g_bt[b][257 + tid] = NEGV;
        __threadfence();
        __syncthreads();
        if (tid == 0) *((volatile int*)&g_flag[b]) = 1;
        return;
    }

    // ---- forward: wait for backward, merge tot = lse_s alpha(tm,s)+bb(tm,s) ----
    if (tid == 0) { while (*((volatile int*)&g_flag[b]) == 0) __nanosleep(32); }
    __syncthreads();
    __threadfence();

    const int q = pair;
    const float b0 = g_bt[b][2 * q + 0];
    const float b1 = g_bt[b][2 * q + 1];
    const float b2 = g_bt[b][2 * q + 2];
    const float b3 = g_bt[b][2 * q + 3];
    const float ve = a_even + lse2(b0, b1);                  // s = 2q
    const bool skipN = (q + 1 < L) &&
                       (targets[b * L + q + 1] != targets[b * L + q]);
    float bbo = lse2(b1, b2);
    if (skipN) bbo = lse2(bbo, b3);
    float c = lse2(ve, a_odd + bbo);                         // + s = 2q+1
    if (finT) c = lse2(c, a_fin + g_bt[b][256]);             // + s = 256

    // block lse-reduce (log2 domain), fixed order
    float mw = c;
    #pragma unroll
    for (int off = 16; off > 0; off >>= 1)
        mw = fmaxf(mw, __shfl_xor_sync(0xFFFFFFFFu, mw, off));
    float sw = ex2f(c - mw);
    #pragma unroll
    for (int off = 16; off > 0; off >>= 1)
        sw += __shfl_xor_sync(0xFFFFFFFFu, sw, off);
    if (lane == 0) sh_red[w] = mw + lg2f(sw);
    __syncthreads();
    if (tid == 0) {
        float tot = sh_red[0];
        #pragma unroll
        for (int i = 1; i < NW; ++i) tot = lse2(tot, sh_red[i]);
        g_partial[b] = tot * LN2;
        *((volatile int*)&g_flag[b]) = 0;      // reset for next replay
    }

    // ---- deterministic final reduction: last forward CTA, fixed order ----
    __threadfence();
    if (tid == 0) s_last = (atomicAdd(&g_ctr, 1) == B - 1) ? 1 : 0;
    __syncthreads();
    if (s_last && w == 0) {
        __threadfence();
        float v = 0.0f;
        for (int i = lane; i < B; i += 32) v += g_partial[i];
        #pragma unroll
        for (int off = 16; off > 0; off >>= 1)
            v += __shfl_down_sync(0xFFFFFFFFu, v, off);
        if (lane == 0) { out[0] = -v; g_ctr = 0; }
    }
    #undef TOF
}

extern "C" void kernel_launch(void* const* d_in, const int* in_sizes, int n_in,
                              void* d_out, int out_size)
{
    const float* lp      = (const float*)d_in[0];   // log_probs [T,B,V] f32
    const int*   targets = (const int*)  d_in[1];   // [B*L] i32
    const int*   ilen    = (const int*)  d_in[2];   // [B] i32
    // d_in[3] = target_lengths (all == L), unused

    const int B = in_sizes[2];
    const int L = in_sizes[1] / B;
    const int V = 1000;                              // fixed problem shape
    const int T = (int)((long long)in_sizes[0] / ((long long)B * V));

    ctc_bidir<<<2 * B, BLOCK>>>(lp, targets, ilen, (float*)d_out, T, B, V, L);
}

// round 14
// speedup vs baseline: 2.6481x; 2.6481x over previous
#include <cuda_runtime.h>
#include <math.h>

#define NEGV  (-1e30f)
#define LOG2E 1.4426950408889634f
#define LN2   0.6931471805599453f
#define MAXL  128
#define NPAIR (MAXL + 2)
#define NW    6
#define BLOCK (NW * 32)        // 192 threads
#define OWN   24
#define HALO  8
#define EROW  132
#define RSLOT 32               // 4 groups of 8 in the ring
#define MAXB  64

__device__ float g_partial[MAXB];
__device__ float g_bt[MAXB][260];     // bt(tm+1, s), log2 domain; [257..259] pad
__device__ int   g_flag[MAXB];        // zero-init; backward sets, forward resets
__device__ int   g_ctr = 0;

__device__ __forceinline__ float ex2f(float x) {
    float r; asm("ex2.approx.ftz.f32 %0, %1;" : "=f"(r) : "f"(x)); return r;
}
__device__ __forceinline__ float lg2f(float x) {
    float r; asm("lg2.approx.ftz.f32 %0, %1;" : "=f"(r) : "f"(x)); return r;
}
__device__ __forceinline__ float lse2(float a, float b) {   // log2 domain
    float m = fmaxf(a, b);
    return m + lg2f(1.0f + ex2f(fminf(a, b) - m));
}
__device__ __forceinline__ unsigned smem_u32(const void* p) {
    return (unsigned)__cvta_generic_to_shared(p);
}
__device__ __forceinline__ void cp4(unsigned dst, const float* src) {
    asm volatile("cp.async.ca.shared.global [%0], [%1], 4;\n" :: "r"(dst), "l"(src));
}
__device__ __forceinline__ void cp_commit() { asm volatile("cp.async.commit_group;\n"); }
__device__ __forceinline__ void cp_wait2()  { asm volatile("cp.async.wait_group 2;\n"); }

__global__ void __launch_bounds__(BLOCK, 1)
ctc_bidir(const float* __restrict__ lp,      // [T, B, V] log-probs (ln domain)
          const int*   __restrict__ targets, // [B, L]
          const int*   __restrict__ ilen,    // [B]
          float* __restrict__ out,
          int T, int B, int V, int L)
{
    const int b    = blockIdx.x >> 1;
    const int dir  = blockIdx.x & 1;          // 0 = forward, 1 = backward
    const int tid  = threadIdx.x;
    const int w    = tid >> 5;
    const int lane = tid & 31;

    __shared__ float sh_e[RSLOT][EROW];
    __shared__ float sh_pa[2][NPAIR];
    __shared__ float sh_po[2][NPAIR];
    __shared__ float sh_red[NW];
    __shared__ int   s_last;

    int Tb = ilen[b];
    if (Tb > T) Tb = T;
    const int tm = Tb >> 1;
    const int N  = dir ? (Tb - tm - 2) : tm;  // live steps k = 1..N

    // pair = 24*w + lane - 8 (lanes 0..7 halo); dir1 works in reflected coords
    const int  pair      = OWN * w + lane - HALO;          // -8 .. 135
    const int  jq        = dir ? (127 - pair) : pair;
    const int  jc        = min(max(jq, 0), L - 1);
    const bool odd_valid = (pair >= 0 && pair < L);
    const int  lab       = targets[b * L + jc];
    bool skip = false;
    if (pair >= 1 && pair < 128) {
        const int oth = dir ? (jc + 1) : (jc - 1);
        skip = (targets[b * L + oth] != lab);
    }

    // loaders: tid<L -> label tid emission, tid==L -> blank
    const bool loader = (tid <= L);
    const float* gsrc = nullptr;
    unsigned dst0 = 0;
    if (loader) {
        const int vv = (tid < L) ? targets[b * L + tid] : 0;
        const int ee = (tid < L) ? (tid + 1)            : 0;
        gsrc = lp + (size_t)b * (size_t)V + vv;
        dst0 = smem_u32(&sh_e[0][ee]);
    }
    const size_t   strideT = (size_t)B * (size_t)V;
    const unsigned rowB    = EROW * sizeof(float);

    #define TOF(k) (dir ? (Tb - 1 - (k)) : (k))

    // prologue: groups for k = 0..31 (4 groups in flight)
    #pragma unroll
    for (int g = 0; g < 4; ++g) {
        if (loader) {
            #pragma unroll
            for (int i = 0; i < 8; ++i) {
                const int k = 8 * g + i;
                if (k <= N) cp4(dst0 + (unsigned)(k & (RSLOT - 1)) * rowB,
                                gsrc + (size_t)TOF(k) * strideT);
            }
        }
        cp_commit();
    }
    cp_wait2();          // groups 0,1 complete
    __syncthreads();

    // init (k=0): fwd alpha(0) on states 0,1; bwd bt(Tb-1) on states 256,255
    float a_even = NEGV, a_odd = NEGV;
    if (pair == 0) { a_even = sh_e[0][0] * LOG2E; a_odd = sh_e[0][1 + jc] * LOG2E; }

    // bootstrap: round-0 emissions into register buffer A (group 0 complete)
    float ebA[8], elA[8], ebB[8], elB[8];
    #pragma unroll
    for (int i = 0; i < 8; ++i) { ebA[i] = sh_e[i][0]; elA[i] = sh_e[i][1 + jc]; }

    // round body: consumes (ebC,elC), preloads round r+1 into (ebN,elN)
    #define ROUND_BODY(r, ebC, elC, ebN, elN)                                     \
    {                                                                             \
        if ((r) > 0 && lane < HALO && pair >= 0) {                                \
            a_even = sh_pa[((r) - 1) & 1][pair];                                  \
            a_odd  = sh_po[((r) - 1) & 1][pair];                                  \
        }                                                                         \
        _Pragma("unroll")                                                         \
        for (int i = 0; i < 8; ++i) {                                             \
            const int slotN = (8 * ((r) + 1) + i) & (RSLOT - 1);                  \
            ebN[i] = sh_e[slotN][0];                                              \
            elN[i] = sh_e[slotN][1 + jc];                                         \
        }                                                                         \
        const int kg = 8 * ((r) + 4);                                             \
        _Pragma("unroll")                                                         \
        for (int i = 0; i < 8; ++i) {                                             \
            const int k = 8 * (r) + i;                                            \
            if (loader && (kg + i) <= N)                                          \
                cp4(dst0 + (unsigned)((kg + i) & (RSLOT - 1)) * rowB,             \
                    gsrc + (size_t)TOF(kg + i) * strideT);                        \
            float po = __shfl_up_sync(0xFFFFFFFFu, a_odd, 1);                     \
            if (pair == 0) po = NEGV;                                             \
            const float qm = fmaxf(a_even, a_odd);                                \
            const float m  = fmaxf(qm, po);                                       \
            const float x  = ex2f(a_even - m);                                    \
            const float z  = ex2f(a_odd  - m);                                    \
            const float y  = ex2f(po     - m);                                    \
            float ne = fmaf(ebC[i], LOG2E, m + lg2f(x + y));                      \
            float no = fmaf(elC[i], LOG2E, m + lg2f((x + z) + (skip ? y : 0.0f)));\
            ne = fmaxf(ne, NEGV);                                                 \
            no = fmaxf(no, NEGV);                                                 \
            const bool live = (k >= 1) && (k <= N);                               \
            a_even = live ? ne : a_even;                                          \
            a_odd  = live ? (odd_valid ? no : NEGV) : a_odd;                      \
        }                                                                         \
        if (lane >= HALO && pair <= L) {                                          \
            sh_pa[(r) & 1][pair] = a_even;                                        \
            sh_po[(r) & 1][pair] = a_odd;                                         \
        }                                                                         \
        cp_commit();                                                              \
        cp_wait2();                                                               \
        __syncthreads();                                                          \
    }

    const int R = (N >> 3) + 1;
    for (int r = 0; r < R; r += 2) {
        ROUND_BODY(r, ebA, elA, ebB, elB)
        if (r + 1 < R) ROUND_BODY(r + 1, ebB, elB, ebA, elA)
    }
    #undef ROUND_BODY

    if (dir) {
        // ---- backward: publish bt(tm+1, .) in natural state order ----
        if (lane >= HALO && pair <= 128) {
            const int qq = 127 - pair;                  // -1 .. 127
            if (qq >= 0) g_bt[b][2 * qq + 1] = a_odd;   // states 1,3,..,255
            g_bt[b][2 * qq + 2] = a_even;               // states 0,2,..,256
        }
        if (tid < 3) g_bt[b][257 + tid] = NEGV;
        __threadfence();
        __syncthreads();
        if (tid == 0) *((volatile int*)&g_flag[b]) = 1;
        return;
    }

    // ---- forward: wait for backward, merge tot = lse_s alpha(tm,s)+bb(tm,s) ----
    if (tid == 0) { while (*((volatile int*)&g_flag[b]) == 0) __nanosleep(32); }
    __syncthreads();
    __threadfence();

    float c = NEGV;
    const bool owner = (lane >= HALO) && (pair >= 0) && (pair <= 128);
    if (owner) {
        const float b0 = g_bt[b][2 * pair + 0];
        const float b1 = g_bt[b][2 * pair + 1];
        const float b2 = g_bt[b][2 * pair + 2];
        const float b3 = g_bt[b][2 * pair + 3];
        const float ve = a_even + lse2(b0, b1);          // s = 2p
        float vo = NEGV;
        if (pair < 128) {
            const bool skipN = (pair + 1 < L) &&
                               (targets[b * L + pair + 1] != targets[b * L + pair]);
            float bbo = lse2(b1, b2);
            if (skipN) bbo = lse2(bbo, b3);
            vo = a_odd + bbo;                            // s = 2p+1
        }
        c = lse2(ve, vo);
    }
    // block lse-reduce (log2 domain), fixed order
    float mw = c;
    #pragma unroll
    for (int off = 16; off > 0; off >>= 1)
        mw = fmaxf(mw, __shfl_xor_sync(0xFFFFFFFFu, mw, off));
    float sw = owner ? ex2f(c - mw) : 0.0f;
    #pragma unroll
    for (int off = 16; off > 0; off >>= 1)
        sw += __shfl_xor_sync(0xFFFFFFFFu, sw, off);
    if (lane == 0) sh_red[w] = mw + lg2f(sw);
    __syncthreads();
    if (tid == 0) {
        float tot = sh_red[0];
        #pragma unroll
        for (int i = 1; i < NW; ++i) tot = lse2(tot, sh_red[i]);
        g_partial[b] = tot * LN2;
        *((volatile int*)&g_flag[b]) = 0;      // reset for next replay
    }

    // ---- deterministic final reduction: last forward CTA, fixed order ----
    __threadfence();
    if (tid == 0) s_last = (atomicAdd(&g_ctr, 1) == B - 1) ? 1 : 0;
    __syncthreads();
    if (s_last && w == 0) {
        __threadfence();
        float v = 0.0f;
        for (int i = lane; i < B; i += 32) v += g_partial[i];
        #pragma unroll
        for (int off = 16; off > 0; off >>= 1)
            v += __shfl_down_sync(0xFFFFFFFFu, v, off);
        if (lane == 0) { out[0] = -v; g_ctr = 0; }
    }
    #undef TOF
}

extern "C" void kernel_launch(void* const* d_in, const int* in_sizes, int n_in,
                              void* d_out, int out_size)
{
    const float* lp      = (const float*)d_in[0];   // log_probs [T,B,V] f32
    const int*   targets = (const int*)  d_in[1];   // [B*L] i32
    const int*   ilen    = (const int*)  d_in[2];   // [B] i32
    // d_in[3] = target_lengths (all == L), unused

    const int B = in_sizes[2];
    const int L = in_sizes[1] / B;
    const int V = 1000;                              // fixed problem shape
    const int T = (int)((long long)in_sizes[0] / ((long long)B * V));

    ctc_bidir<<<2 * B, BLOCK>>>(lp, targets, ilen, (float*)d_out, T, B, V, L);
}